// round 3
// baseline (speedup 1.0000x reference)
#include <cuda_runtime.h>
#include <cstdint>

// Problem dims (fixed by the benchmark's setup_inputs)
#define T_TOK 8192
#define H_DIM 2048
#define I_DIM 4096
#define E_NUM 8

#define SWIGLU_ALPHA 1.702f
#define SWIGLU_LIMIT 7.0f

// 134 MB activation scratch (static __device__ — no allocation in kernel_launch)
__device__ __align__(128) float g_act[(size_t)T_TOK * (size_t)I_DIM];

// ---------------------------------------------------------------------------
// helpers
// ---------------------------------------------------------------------------
__device__ __forceinline__ unsigned f2tf32(float f) {
    unsigned u;
    asm volatile("cvt.rna.tf32.f32 %0, %1;" : "=r"(u) : "f"(f));
    return u;
}

__device__ __forceinline__ void mma_tf32(float c[4],
                                         unsigned a0, unsigned a1, unsigned a2, unsigned a3,
                                         unsigned b0, unsigned b1) {
    asm volatile(
        "mma.sync.aligned.m16n8k8.row.col.f32.tf32.tf32.f32 "
        "{%0,%1,%2,%3}, {%4,%5,%6,%7}, {%8,%9}, {%0,%1,%2,%3};\n"
        : "+f"(c[0]), "+f"(c[1]), "+f"(c[2]), "+f"(c[3])
        : "r"(a0), "r"(a1), "r"(a2), "r"(a3), "r"(b0), "r"(b1));
}

__device__ __forceinline__ void cp_async16(uint32_t smem_addr, const void* gmem) {
    asm volatile("cp.async.cg.shared.global [%0], [%1], 16;\n" :: "r"(smem_addr), "l"(gmem));
}
__device__ __forceinline__ void cp_commit() { asm volatile("cp.async.commit_group;\n"); }
template <int N>
__device__ __forceinline__ void cp_wait() { asm volatile("cp.async.wait_group %0;\n" :: "n"(N)); }

__device__ __forceinline__ float swiglu_act(float gt, float u) {
    gt = fminf(gt, SWIGLU_LIMIT);
    u  = fminf(fmaxf(u, -SWIGLU_LIMIT), SWIGLU_LIMIT);
    float sig = 1.0f / (1.0f + __expf(-SWIGLU_ALPHA * gt));
    return (u + 1.0f) * (gt * sig);
}

// ---------------------------------------------------------------------------
// Kernel 1: fused gate+up GEMM + bias + SwiGLU -> g_act
// Tile: BM=128, BN=128, BK=32. 256 threads = 8 warps (2 x 4), warp tile 64x32.
// ---------------------------------------------------------------------------
#define BM 128
#define BK 32
#define BN1 128
#define LDA 36            // A smem stride (floats): bank = (4m + k) % 32, conflict-free
#define LDB1 136          // B smem stride (floats): bank = (8k + n) % 32, conflict-free
#define A_FLOATS (BM * LDA)                 // 4608
#define B1_FLOATS (BK * LDB1)               // 4352
#define BUF1 (A_FLOATS + 2 * B1_FLOATS)     // 13312 floats per buffer
#define SMEM1_BYTES (2 * BUF1 * 4)          // 106496 B

extern "C" __global__ void __launch_bounds__(256, 1)
fused_gate_up_kernel(const float* __restrict__ x,
                     const int*   __restrict__ offs,
                     const float* __restrict__ gate_w,
                     const float* __restrict__ up_w,
                     const float* __restrict__ gate_b,
                     const float* __restrict__ up_b)
{
    extern __shared__ float smem[];
    const int tid = threadIdx.x;
    const int wid = tid >> 5, lane = tid & 31;
    const int g = lane >> 2, tg = lane & 3;       // groupID, threadID-in-group
    const int warp_m = wid >> 2, warp_n = wid & 3;
    const int m0 = blockIdx.y * BM;
    const int n0 = blockIdx.x * BN1;

    // expert for this row block (offsets are cumulative end offsets)
    int e = 0;
    while (e < E_NUM - 1 && __ldg(&offs[e]) <= m0) ++e;

    const float* Wg = gate_w + (size_t)e * H_DIM * I_DIM;
    const float* Wu = up_w   + (size_t)e * H_DIM * I_DIM;

    float accG[4][4][4];
    float accU[4][4][4];
#pragma unroll
    for (int i = 0; i < 4; i++)
#pragma unroll
        for (int j = 0; j < 4; j++)
#pragma unroll
            for (int k = 0; k < 4; k++) { accG[i][j][k] = 0.f; accU[i][j][k] = 0.f; }

    const uint32_t smem_u = (uint32_t)__cvta_generic_to_shared(smem);

    auto load_tile = [&](int kt, int buf) {
        const int k0 = kt * BK;
        const uint32_t base = smem_u + (uint32_t)buf * (BUF1 * 4);
        // A: 128x32 floats = 1024 float4, 4 per thread
#pragma unroll
        for (int i = 0; i < 4; i++) {
            int idx = tid + i * 256;
            int row = idx >> 3, kc = idx & 7;
            cp_async16(base + (uint32_t)(row * LDA + kc * 4) * 4,
                       x + (size_t)(m0 + row) * H_DIM + k0 + kc * 4);
        }
        // Bg, Bu: each 32x128 floats = 1024 float4, 4 per thread each
#pragma unroll
        for (int i = 0; i < 4; i++) {
            int idx = tid + i * 256;
            int kr = idx >> 5, nc = idx & 31;
            size_t goff = (size_t)(k0 + kr) * I_DIM + n0 + nc * 4;
            cp_async16(base + (uint32_t)(A_FLOATS + kr * LDB1 + nc * 4) * 4, Wg + goff);
            cp_async16(base + (uint32_t)(A_FLOATS + B1_FLOATS + kr * LDB1 + nc * 4) * 4, Wu + goff);
        }
        cp_commit();
    };

    load_tile(0, 0);
    const int KT = H_DIM / BK;
    for (int kt = 0; kt < KT; ++kt) {
        const int cur = kt & 1;
        if (kt + 1 < KT) { load_tile(kt + 1, cur ^ 1); cp_wait<1>(); }
        else             { cp_wait<0>(); }
        __syncthreads();

        const float* As = smem + cur * BUF1;
        const float* Bg = As + A_FLOATS;
        const float* Bu = Bg + B1_FLOATS;

#pragma unroll
        for (int kk = 0; kk < 4; ++kk) {
            const int k8 = kk * 8;
            unsigned a[4][4];
#pragma unroll
            for (int mt = 0; mt < 4; ++mt) {
                int r = warp_m * 64 + mt * 16 + g;
                a[mt][0] = f2tf32(As[r * LDA + k8 + tg]);
                a[mt][1] = f2tf32(As[(r + 8) * LDA + k8 + tg]);
                a[mt][2] = f2tf32(As[r * LDA + k8 + tg + 4]);
                a[mt][3] = f2tf32(As[(r + 8) * LDA + k8 + tg + 4]);
            }
            unsigned bg[4][2], bu[4][2];
#pragma unroll
            for (int nt = 0; nt < 4; ++nt) {
                int c = warp_n * 32 + nt * 8 + g;
                bg[nt][0] = f2tf32(Bg[(k8 + tg) * LDB1 + c]);
                bg[nt][1] = f2tf32(Bg[(k8 + tg + 4) * LDB1 + c]);
                bu[nt][0] = f2tf32(Bu[(k8 + tg) * LDB1 + c]);
                bu[nt][1] = f2tf32(Bu[(k8 + tg + 4) * LDB1 + c]);
            }
#pragma unroll
            for (int mt = 0; mt < 4; ++mt)
#pragma unroll
                for (int nt = 0; nt < 4; ++nt) {
                    mma_tf32(accG[mt][nt], a[mt][0], a[mt][1], a[mt][2], a[mt][3], bg[nt][0], bg[nt][1]);
                    mma_tf32(accU[mt][nt], a[mt][0], a[mt][1], a[mt][2], a[mt][3], bu[nt][0], bu[nt][1]);
                }
        }
        __syncthreads();
    }

    // epilogue: bias + SwiGLU -> g_act (fp32, row-major T x I)
    const float* gb = gate_b + (size_t)e * I_DIM;
    const float* ub = up_b   + (size_t)e * I_DIM;
#pragma unroll
    for (int mt = 0; mt < 4; ++mt) {
        int r0 = m0 + warp_m * 64 + mt * 16 + g;
#pragma unroll
        for (int nt = 0; nt < 4; ++nt) {
            int c = n0 + warp_n * 32 + nt * 8 + tg * 2;
            float gb0 = gb[c], gb1 = gb[c + 1];
            float ub0 = ub[c], ub1 = ub[c + 1];
            float2 v0, v1;
            v0.x = swiglu_act(accG[mt][nt][0] + gb0, accU[mt][nt][0] + ub0);
            v0.y = swiglu_act(accG[mt][nt][1] + gb1, accU[mt][nt][1] + ub1);
            v1.x = swiglu_act(accG[mt][nt][2] + gb0, accU[mt][nt][2] + ub0);
            v1.y = swiglu_act(accG[mt][nt][3] + gb1, accU[mt][nt][3] + ub1);
            *reinterpret_cast<float2*>(&g_act[(size_t)r0 * I_DIM + c])        = v0;
            *reinterpret_cast<float2*>(&g_act[(size_t)(r0 + 8) * I_DIM + c])  = v1;
        }
    }
}

// ---------------------------------------------------------------------------
// Kernel 2: down GEMM (g_act @ down_w + down_b) -> out
// Tile: BM=128, BN=256, BK=32. 8 warps (2 x 4), warp tile 64x64.
// ---------------------------------------------------------------------------
#define BN2 256
#define LDB2 264          // bank = (8k + n) % 32, conflict-free
#define B2_FLOATS (BK * LDB2)               // 8448
#define BUF2 (A_FLOATS + B2_FLOATS)         // 13056 floats
#define SMEM2_BYTES (2 * BUF2 * 4)          // 104448 B

extern "C" __global__ void __launch_bounds__(256, 1)
down_kernel(const int*   __restrict__ offs,
            const float* __restrict__ down_w,
            const float* __restrict__ down_b,
            float*       __restrict__ out)
{
    extern __shared__ float smem[];
    const int tid = threadIdx.x;
    const int wid = tid >> 5, lane = tid & 31;
    const int g = lane >> 2, tg = lane & 3;
    const int warp_m = wid >> 2, warp_n = wid & 3;
    const int m0 = blockIdx.y * BM;
    const int n0 = blockIdx.x * BN2;

    int e = 0;
    while (e < E_NUM - 1 && __ldg(&offs[e]) <= m0) ++e;

    const float* A  = g_act;
    const float* Wd = down_w + (size_t)e * I_DIM * H_DIM;

    float acc[4][8][4];
#pragma unroll
    for (int i = 0; i < 4; i++)
#pragma unroll
        for (int j = 0; j < 8; j++)
#pragma unroll
            for (int k = 0; k < 4; k++) acc[i][j][k] = 0.f;

    const uint32_t smem_u = (uint32_t)__cvta_generic_to_shared(smem);

    auto load_tile = [&](int kt, int buf) {
        const int k0 = kt * BK;
        const uint32_t base = smem_u + (uint32_t)buf * (BUF2 * 4);
#pragma unroll
        for (int i = 0; i < 4; i++) {
            int idx = tid + i * 256;
            int row = idx >> 3, kc = idx & 7;
            cp_async16(base + (uint32_t)(row * LDA + kc * 4) * 4,
                       A + (size_t)(m0 + row) * I_DIM + k0 + kc * 4);
        }
        // B: 32 x 256 floats = 2048 float4, 8 per thread
#pragma unroll
        for (int i = 0; i < 8; i++) {
            int idx = tid + i * 256;
            int kr = idx >> 6, nc = idx & 63;
            cp_async16(base + (uint32_t)(A_FLOATS + kr * LDB2 + nc * 4) * 4,
                       Wd + (size_t)(k0 + kr) * H_DIM + n0 + nc * 4);
        }
        cp_commit();
    };

    load_tile(0, 0);
    const int KT = I_DIM / BK;
    for (int kt = 0; kt < KT; ++kt) {
        const int cur = kt & 1;
        if (kt + 1 < KT) { load_tile(kt + 1, cur ^ 1); cp_wait<1>(); }
        else             { cp_wait<0>(); }
        __syncthreads();

        const float* As = smem + cur * BUF2;
        const float* Bs = As + A_FLOATS;

#pragma unroll
        for (int kk = 0; kk < 4; ++kk) {
            const int k8 = kk * 8;
            unsigned a[4][4];
#pragma unroll
            for (int mt = 0; mt < 4; ++mt) {
                int r = warp_m * 64 + mt * 16 + g;
                a[mt][0] = f2tf32(As[r * LDA + k8 + tg]);
                a[mt][1] = f2tf32(As[(r + 8) * LDA + k8 + tg]);
                a[mt][2] = f2tf32(As[r * LDA + k8 + tg + 4]);
                a[mt][3] = f2tf32(As[(r + 8) * LDA + k8 + tg + 4]);
            }
            unsigned b[8][2];
#pragma unroll
            for (int nt = 0; nt < 8; ++nt) {
                int c = warp_n * 64 + nt * 8 + g;
                b[nt][0] = f2tf32(Bs[(k8 + tg) * LDB2 + c]);
                b[nt][1] = f2tf32(Bs[(k8 + tg + 4) * LDB2 + c]);
            }
#pragma unroll
            for (int mt = 0; mt < 4; ++mt)
#pragma unroll
                for (int nt = 0; nt < 8; ++nt)
                    mma_tf32(acc[mt][nt], a[mt][0], a[mt][1], a[mt][2], a[mt][3], b[nt][0], b[nt][1]);
        }
        __syncthreads();
    }

    const float* db = down_b + (size_t)e * H_DIM;
#pragma unroll
    for (int mt = 0; mt < 4; ++mt) {
        int r0 = m0 + warp_m * 64 + mt * 16 + g;
#pragma unroll
        for (int nt = 0; nt < 8; ++nt) {
            int c = n0 + warp_n * 64 + nt * 8 + tg * 2;
            float b0 = db[c], b1 = db[c + 1];
            float2 v0, v1;
            v0.x = acc[mt][nt][0] + b0;
            v0.y = acc[mt][nt][1] + b1;
            v1.x = acc[mt][nt][2] + b0;
            v1.y = acc[mt][nt][3] + b1;
            *reinterpret_cast<float2*>(&out[(size_t)r0 * H_DIM + c])       = v0;
            *reinterpret_cast<float2*>(&out[(size_t)(r0 + 8) * H_DIM + c]) = v1;
        }
    }
}

// ---------------------------------------------------------------------------
// launch
// ---------------------------------------------------------------------------
extern "C" void kernel_launch(void* const* d_in, const int* in_sizes, int n_in,
                              void* d_out, int out_size)
{
    const float* x      = (const float*)d_in[0];
    const int*   offs   = (const int*)  d_in[1];
    const float* gate_w = (const float*)d_in[2];
    const float* up_w   = (const float*)d_in[3];
    const float* down_w = (const float*)d_in[4];
    const float* gate_b = (const float*)d_in[5];
    const float* up_b   = (const float*)d_in[6];
    const float* down_b = (const float*)d_in[7];
    float* out = (float*)d_out;

    cudaFuncSetAttribute(fused_gate_up_kernel,
                         cudaFuncAttributeMaxDynamicSharedMemorySize, SMEM1_BYTES);
    cudaFuncSetAttribute(down_kernel,
                         cudaFuncAttributeMaxDynamicSharedMemorySize, SMEM2_BYTES);

    dim3 grid1(I_DIM / BN1, T_TOK / BM);   // (32, 64)
    fused_gate_up_kernel<<<grid1, 256, SMEM1_BYTES>>>(x, offs, gate_w, up_w, gate_b, up_b);

    dim3 grid2(H_DIM / BN2, T_TOK / BM);   // (8, 64)
    down_kernel<<<grid2, 256, SMEM2_BYTES>>>(offs, down_w, down_b, out);
}